// round 13
// baseline (speedup 1.0000x reference)
#include <cuda_runtime.h>
#include <cstdint>

#define NB 128
#define NV 128000
#define KTOP 20
#define NTHREADS 1024
#define CAP 4096
#define THRESH 3.0f

__device__ __forceinline__ float fast_ex2(float x) {
    float r; asm("ex2.approx.ftz.f32 %0, %1;" : "=f"(r) : "f"(x)); return r;
}
__device__ __forceinline__ float fast_lg2(float x) {
    float r; asm("lg2.approx.ftz.f32 %0, %1;" : "=f"(r) : "f"(x)); return r;
}

// Streaming vec4 load pinned in SASS order (asm volatile).
__device__ __forceinline__ float4 ldg_cs4(const float4* p) {
    float4 v;
    asm volatile("ld.global.cs.v4.f32 {%0,%1,%2,%3}, [%4];"
                 : "=f"(v.x), "=f"(v.y), "=f"(v.z), "=f"(v.w) : "l"(p));
    return v;
}

// ---- packed f32x2 helpers (sm_100+) ----
__device__ __forceinline__ unsigned long long pk2(float lo, float hi) {
    unsigned long long r; asm("mov.b64 %0, {%1, %2};" : "=l"(r) : "f"(lo), "f"(hi)); return r;
}
__device__ __forceinline__ void up2(unsigned long long v, float& lo, float& hi) {
    asm("mov.b64 {%0, %1}, %2;" : "=f"(lo), "=f"(hi) : "l"(v));
}
__device__ __forceinline__ unsigned long long mul2(unsigned long long a, unsigned long long b) {
    unsigned long long r; asm("mul.rn.f32x2 %0, %1, %2;" : "=l"(r) : "l"(a), "l"(b)); return r;
}
__device__ __forceinline__ unsigned long long add2(unsigned long long a, unsigned long long b) {
    unsigned long long r; asm("add.rn.f32x2 %0, %1, %2;" : "=l"(r) : "l"(a), "l"(b)); return r;
}
__device__ __forceinline__ unsigned long long fma2(unsigned long long a, unsigned long long b, unsigned long long c) {
    unsigned long long r; asm("fma.rn.f32x2 %0, %1, %2, %3;" : "=l"(r) : "l"(a), "l"(b), "l"(c)); return r;
}

// Monotone pack: larger value wins; on equal value, SMALLER index wins (jax tie rule).
__device__ __forceinline__ unsigned long long packkey(float v, int idx) {
    unsigned fb = __float_as_uint(v);
    fb = (fb & 0x80000000u) ? ~fb : (fb | 0x80000000u);
    return ((unsigned long long)fb << 32) | (unsigned long long)(~(unsigned)idx);
}

// Accurate -ln(u) for u in (0,1): poly(log1p) near 1, MUFU lg2 elsewhere.
__device__ __forceinline__ float neg_log(float u) {
    float d = u - 1.0f;
    float p = fmaf(d, 0.2f, -0.25f);
    p = fmaf(d, p, 0.333333333f);
    p = fmaf(d, p, -0.5f);
    p = fmaf(d, p, 1.0f);
    float lp = -d * p;                        // -log1p(d), good for d in (-0.16, 0]
    float lm = -0.693147181f * fast_lg2(u);
    return (u > 0.84f) ? lp : lm;
}

__global__ __launch_bounds__(NTHREADS) void sampler_kernel(
    const float* __restrict__ logits,
    const float* __restrict__ temp,
    const float* __restrict__ u,
    float* __restrict__ out)
{
    const int b   = blockIdx.x;
    const int tid = threadIdx.x;

    __shared__ float s_val[CAP];
    __shared__ int   s_idx[CAP];
    __shared__ int   s_cnt;
    __shared__ float s_warp[NTHREADS / 32];
    __shared__ unsigned long long s_gkey;
    __shared__ unsigned long long s_win;
    __shared__ float s_lse;
    __shared__ float s_selval[KTOP];
    __shared__ int   s_selidx[KTOP];

    if (tid == 0) { s_cnt = 0; s_gkey = 0ull; }
    __syncthreads();

    const float t      = temp[b];
    const bool  greedy = (t < 1e-5f);
    const float tt     = greedy ? 1.0f : t;
    const float inv_t  = 1.0f / tt;
    const float c      = inv_t * 1.44269504088896f;
    const unsigned long long c2 = pk2(c, c);

    const float4* __restrict__ lg4 = (const float4*)(logits + (size_t)b * NV);
    const float4* __restrict__ u4  = (const float4*)(u      + (size_t)b * NV);

    unsigned long long accA = pk2(0.0f, 0.0f);
    unsigned long long accB = pk2(0.0f, 0.0f);
    float best_e  = 0.0f;
    float best_lq = 1.0f;
    int   best_gi = 0;
    float invK    = 1e30f;
    unsigned long long k2 = pk2(invK, invK);

    // Exact per-element rare path. Gumbel check uses CURRENT invK (exact R9
    // semantics); updates invK and its packed mirror k2.
    #define RARE(lv, uv, ee, gidx)                                                  \
    {                                                                               \
        if ((lv) > THRESH) {                                                        \
            int p = atomicAdd(&s_cnt, 1);                                           \
            if (p < CAP) { s_val[p] = (lv); s_idx[p] = (gidx); }                    \
        }                                                                           \
        if (fmaf((ee), invK, (uv)) > 0.999f) {                                      \
            float lq = neg_log(uv);                                                 \
            if ((ee) * best_lq > best_e * lq) {                                     \
                best_e = (ee); best_lq = lq; best_gi = (gidx);                      \
                invK = 1.01f * (lq / (ee));                                         \
                k2 = pk2(invK, invK);                                               \
            }                                                                       \
        }                                                                           \
    }
    // Per-element trigger using precomputed packed h (h computed with the invK
    // valid at the top of this vec4 — a superset when invK has since shrunk;
    // RARE re-checks exactly, so results are identical to R9).
    #define ELEM(lv, uv, ee, hh, gidx)                                              \
    {                                                                               \
        bool hot = ((lv) > THRESH) | ((hh) > 0.999f);                               \
        if (hot) RARE(lv, uv, ee, gidx)                                             \
    }
    #define PROC(L, U, goff)                                                        \
    {                                                                               \
        unsigned long long lx = pk2(L.x, L.y), lz = pk2(L.z, L.w);                  \
        unsigned long long x01 = mul2(lx, c2), x23 = mul2(lz, c2);                  \
        float x0, x1, x2, x3; up2(x01, x0, x1); up2(x23, x2, x3);                   \
        float e0 = fast_ex2(x0), e1 = fast_ex2(x1);                                 \
        float e2 = fast_ex2(x2), e3 = fast_ex2(x3);                                 \
        unsigned long long e01 = pk2(e0, e1), e23 = pk2(e2, e3);                    \
        accA = add2(accA, e01); accB = add2(accB, e23);                             \
        unsigned long long u01 = pk2(U.x, U.y), u23 = pk2(U.z, U.w);                \
        unsigned long long h01 = fma2(e01, k2, u01), h23 = fma2(e23, k2, u23);      \
        float h0, h1, h2, h3; up2(h01, h0, h1); up2(h23, h2, h3);                   \
        ELEM(L.x, U.x, e0, h0, (goff) + 0) ELEM(L.y, U.y, e1, h1, (goff) + 1)       \
        ELEM(L.z, U.z, e2, h2, (goff) + 2) ELEM(L.w, U.w, e3, h3, (goff) + 3)       \
    }

    const int nvec = NV / 4;   // 32000
    int i = tid;
    // Proven R9 shell: 3-deep pinned batches, warp-uniform guards.
    for (; i + 2 * NTHREADS < nvec; i += 3 * NTHREADS) {
        float4 L0 = ldg_cs4(lg4 + i);
        float4 U0 = ldg_cs4(u4  + i);
        float4 L1 = ldg_cs4(lg4 + i + NTHREADS);
        float4 U1 = ldg_cs4(u4  + i + NTHREADS);
        float4 L2 = ldg_cs4(lg4 + i + 2 * NTHREADS);
        float4 U2 = ldg_cs4(u4  + i + 2 * NTHREADS);

        PROC(L0, U0, 4 * i)
        PROC(L1, U1, 4 * (i + NTHREADS))
        PROC(L2, U2, 4 * (i + 2 * NTHREADS))
    }
    for (; i < nvec; i += NTHREADS) {   // remainder, 1-deep
        float4 L0 = ldg_cs4(lg4 + i);
        float4 U0 = ldg_cs4(u4  + i);
        PROC(L0, U0, 4 * i)
    }
    #undef PROC
    #undef ELEM
    #undef RARE

    // ---- sumexp reduction (fixed order -> deterministic) ----
    float a0, a1, b0v, b1v;
    up2(accA, a0, a1); up2(accB, b0v, b1v);
    float sumexp = (a0 + a1) + (b0v + b1v);
    #pragma unroll
    for (int o = 16; o; o >>= 1) sumexp += __shfl_down_sync(0xFFFFFFFFu, sumexp, o);
    if ((tid & 31) == 0) s_warp[tid >> 5] = sumexp;

    // ---- Gumbel winner across threads ----
    atomicMax(&s_gkey, packkey(best_e / best_lq, best_gi));
    __syncthreads();

    if (tid == 0) {
        float s = 0.0f;
        #pragma unroll
        for (int w = 0; w < NTHREADS / 32; w++) s += s_warp[w];
        s_lse = 0.693147181f * fast_lg2(s);
    }

    // ---- top-K: single-pass rank selection over shared candidates ----
    const int cnt = s_cnt;
    const bool okc = (cnt >= KTOP) && (cnt <= CAP);
    if (okc) {
        for (int p = tid; p < cnt; p += NTHREADS) {
            float v = s_val[p]; int ix = s_idx[p];
            unsigned long long my = packkey(v, ix);
            int rank = 0;
            for (int j = 0; j < cnt; j++)
                rank += (packkey(s_val[j], s_idx[j]) > my) ? 1 : 0;
            if (rank < KTOP) { s_selval[rank] = v; s_selidx[rank] = ix; }
        }
    } else {
        // robust fallback: 20 rounds of global argmax with exclusion (statistically never)
        unsigned long long bound = 0xFFFFFFFFFFFFFFFFull;
        const float* lrow = logits + (size_t)b * NV;
        for (int r = 0; r < KTOP; r++) {
            __syncthreads();
            if (tid == 0) s_win = 0ull;
            __syncthreads();
            unsigned long long loc = 0ull;
            for (int p = tid; p < NV; p += NTHREADS) {
                unsigned long long k = packkey(lrow[p], p);
                if (k < bound && k > loc) loc = k;
            }
            if (loc) atomicMax(&s_win, loc);
            __syncthreads();
            unsigned long long w = s_win;
            bound = w;
            if (tid == 0) {
                unsigned fb = (unsigned)(w >> 32);
                fb = (fb & 0x80000000u) ? (fb ^ 0x80000000u) : ~fb;
                s_selval[r] = __uint_as_float(fb);
                s_selidx[r] = (int)(~(unsigned)(w & 0xFFFFFFFFull));
            }
        }
    }
    __syncthreads();

    // ---- outputs: [sampled(NB) | topk_logprobs(NB*K) | topk_indices(NB*K)] ----
    if (tid < KTOP) {
        float lp = s_selval[tid] * inv_t - s_lse;
        out[NB + b * KTOP + tid]             = lp;
        out[NB + NB * KTOP + b * KTOP + tid] = (float)s_selidx[tid];
    }
    if (tid == 0) {
        int gi = (int)(~(unsigned)(s_gkey & 0xFFFFFFFFull));
        out[b] = (float)(greedy ? s_selidx[0] : gi);
    }
}

extern "C" void kernel_launch(void* const* d_in, const int* in_sizes, int n_in,
                              void* d_out, int out_size) {
    const float* logits = (const float*)d_in[0];
    const float* temp   = (const float*)d_in[1];
    const float* u      = (const float*)d_in[2];
    (void)in_sizes; (void)n_in; (void)out_size;
    sampler_kernel<<<NB, NTHREADS>>>(logits, temp, u, (float*)d_out);
}